// round 11
// baseline (speedup 1.0000x reference)
#include <cuda_runtime.h>
#include <cuda_fp16.h>
#include <math.h>
#include <cstdint>

// Problem constants
#define BATCH 4
#define SEQ   2048
#define HID   1024
#define NHEAD 16
#define DK    64
#define DFF   4096
#define MTOT  (BATCH * SEQ)          // 8192 rows
#define NQKV  (3 * HID)              // 3072

// ---------------------------------------------------------------------------
// Scratch
// ---------------------------------------------------------------------------
__device__ __half g_xh  [MTOT * HID];
__device__ __half g_qkvh[MTOT * NQKV];
__device__ __half g_ctxh[MTOT * HID];
__device__ float  g_ao  [MTOT * HID];
__device__ float  g_x1  [MTOT * HID];
__device__ __half g_x1h [MTOT * HID];
__device__ __half g_hh  [MTOT * DFF];
__device__ float  g_ff  [MTOT * HID];
__device__ __half g_wqkvt[NQKV * HID];
__device__ __half g_wot [HID * HID];
__device__ __half g_w1t [HID * DFF];
__device__ __half g_w2t [DFF * HID];
__device__ float  g_bqkv[NQKV];

// ---------------------------------------------------------------------------
// helpers
// ---------------------------------------------------------------------------
__device__ __forceinline__ uint32_t smem_u32(const void* p) {
    uint32_t a;
    asm("{ .reg .u64 t; cvta.to.shared.u64 t, %1; cvt.u32.u64 %0, t; }" : "=r"(a) : "l"(p));
    return a;
}
__device__ __forceinline__ void cp_async16(uint32_t saddr, const void* gaddr) {
    asm volatile("cp.async.cg.shared.global [%0], [%1], 16;" :: "r"(saddr), "l"(gaddr) : "memory");
}
#define CP_COMMIT() asm volatile("cp.async.commit_group;" ::: "memory")
#define CP_WAIT(n)  asm volatile("cp.async.wait_group %0;" :: "n"(n) : "memory")

__device__ __forceinline__ void mma_f16(
    float& d0, float& d1, float& d2, float& d3,
    uint32_t a0, uint32_t a1, uint32_t a2, uint32_t a3,
    uint32_t b0, uint32_t b1)
{
    asm volatile(
        "mma.sync.aligned.m16n8k16.row.col.f32.f16.f16.f32 "
        "{%0,%1,%2,%3}, {%4,%5,%6,%7}, {%8,%9}, {%0,%1,%2,%3};"
        : "+f"(d0), "+f"(d1), "+f"(d2), "+f"(d3)
        : "r"(a0), "r"(a1), "r"(a2), "r"(a3), "r"(b0), "r"(b1));
}
__device__ __forceinline__ void ldmatrix_x4(
    uint32_t& r0, uint32_t& r1, uint32_t& r2, uint32_t& r3, uint32_t addr)
{
    asm volatile("ldmatrix.sync.aligned.m8n8.x4.shared.b16 {%0,%1,%2,%3}, [%4];"
                 : "=r"(r0), "=r"(r1), "=r"(r2), "=r"(r3) : "r"(addr));
}
__device__ __forceinline__ void ldmatrix_x4_trans(
    uint32_t& r0, uint32_t& r1, uint32_t& r2, uint32_t& r3, uint32_t addr)
{
    asm volatile("ldmatrix.sync.aligned.m8n8.x4.trans.shared.b16 {%0,%1,%2,%3}, [%4];"
                 : "=r"(r0), "=r"(r1), "=r"(r2), "=r"(r3) : "r"(addr));
}

__device__ __forceinline__ float gelu_fn(float x) {
    const float c = 0.7978845608028654f;
    float x3 = x * x * x;
    return 0.5f * x * (1.0f + tanhf(c * (x + 0.044715f * x3)));
}

// ---------------------------------------------------------------------------
// Fused prep kernel (transposes + x conversion + bias concat)
// ---------------------------------------------------------------------------
__device__ __forceinline__ void transpose_tile(
    float (*t)[33], const float* __restrict__ W, __half* __restrict__ Wt,
    int K, int N, int bx, int by, int tid)
{
    const int tx = tid & 31;
    const int ty = tid >> 5;
    const int b0 = bx * 32, k0 = by * 32;
#pragma unroll
    for (int q = 0; q < 4; q++)
        t[ty + q * 8][tx] = W[(size_t)(k0 + ty + q * 8) * N + b0 + tx];
    __syncthreads();
#pragma unroll
    for (int q = 0; q < 4; q++)
        Wt[(size_t)(b0 + ty + q * 8) * K + k0 + tx] = __float2half_rn(t[tx][ty + q * 8]);
}

__global__ void __launch_bounds__(256) prep_kernel(
    const float* __restrict__ Wq, const float* __restrict__ Wk,
    const float* __restrict__ Wv, const float* __restrict__ Wo,
    const float* __restrict__ W1, const float* __restrict__ W2,
    const float* __restrict__ x,
    const float* __restrict__ bq, const float* __restrict__ bk,
    const float* __restrict__ bv)
{
    __shared__ float t[32][33];
    const int id  = blockIdx.x;
    const int tid = threadIdx.x;

    if (id < 4096) {
        const int m = id >> 10;
        const float* W = (m == 0) ? Wq : (m == 1) ? Wk : (m == 2) ? Wv : Wo;
        __half* Wt = (m == 0) ? g_wqkvt
                   : (m == 1) ? g_wqkvt + (size_t)HID * HID
                   : (m == 2) ? g_wqkvt + (size_t)2 * HID * HID
                   : g_wot;
        const int lid = id & 1023;
        transpose_tile(t, W, Wt, HID, HID, lid & 31, lid >> 5, tid);
    } else if (id < 8192) {
        const int lid = id - 4096;
        transpose_tile(t, W1, g_w1t, HID, DFF, lid & 127, lid >> 7, tid);
    } else if (id < 12288) {
        const int lid = id - 8192;
        transpose_tile(t, W2, g_w2t, DFF, HID, lid & 31, lid >> 5, tid);
    } else if (id < 16384) {
        const int i = ((id - 12288) * 256 + tid) * 8;
        float4 a = *(const float4*)&x[i];
        float4 b = *(const float4*)&x[i + 4];
        __half2 h[4];
        h[0] = __floats2half2_rn(a.x, a.y);
        h[1] = __floats2half2_rn(a.z, a.w);
        h[2] = __floats2half2_rn(b.x, b.y);
        h[3] = __floats2half2_rn(b.z, b.w);
        *(uint4*)&g_xh[i] = *(uint4*)h;
    } else {
        const int i = (id - 16384) * 256 + tid;      // 0..3071
        const int seg = i >> 10, off = i & 1023;
        g_bqkv[i] = (seg == 0) ? bq[off] : (seg == 1) ? bk[off] : bv[off];
    }
}

// ---------------------------------------------------------------------------
// fp16 mma.sync GEMM:  C[M,N] = A[M,K] @ W[K,N] + bias   (W given as Wt[n][k])
// CTA tile 128x256, 512 threads = 16 warps (4m x 4n), warp tile 32x64,
// BK=64, 3-stage cp.async pipeline. ~118 regs/thread, smem 165.9KB, 1 CTA/SM.
// EPI: 0 = fp32 out, 1 = half out, 2 = half out + GELU
// ---------------------------------------------------------------------------
#define HPAD 72
#define BM 128
#define BN 256
#define NTHR 512
#define STAGE_H ((BM + BN) * HPAD)                    // halves per stage
#define GEMM_SMEM (3 * STAGE_H * 2)                   // 165888 bytes

__device__ __forceinline__ void fill_stage(
    __half* As, __half* Bs, const __half* A, const __half* Bt,
    int bm, int bn, int k0, int K, int tid)
{
#pragma unroll
    for (int q = 0; q < 2; q++) {           // A: 128 rows x 8 chunks = 1024
        int idx = q * NTHR + tid;
        int row = idx >> 3, c = idx & 7;
        cp_async16(smem_u32(&As[row * HPAD + c * 8]),
                   &A[(size_t)(bm + row) * K + k0 + c * 8]);
    }
#pragma unroll
    for (int q = 0; q < 4; q++) {           // B: 256 rows x 8 chunks = 2048
        int idx = q * NTHR + tid;
        int row = idx >> 3, c = idx & 7;
        cp_async16(smem_u32(&Bs[row * HPAD + c * 8]),
                   &Bt[(size_t)(bn + row) * K + k0 + c * 8]);
    }
}

template<int EPI>
__global__ void __launch_bounds__(NTHR) mma_gemm_h(
    const __half* __restrict__ A, const __half* __restrict__ Bt,
    const float* __restrict__ bias, void* __restrict__ Cout,
    int M, int N, int K)
{
    extern __shared__ __half shh[];
    const int tid  = threadIdx.x;
    const int wid  = tid >> 5;
    const int lane = tid & 31;
    const int g    = lane >> 2;
    const int t    = lane & 3;
    const int bm   = blockIdx.y * BM;
    const int bn   = blockIdx.x * BN;
    const int moff = (wid & 3) * 32;       // 4 warps in m
    const int noff = (wid >> 2) * 64;      // 4 warps in n

    const int a_r = lane & 15;
    const int a_c = (lane >> 4) * 8;
    const int b_r = (lane & 7) + ((lane >> 4) << 3);
    const int b_c = ((lane >> 3) & 1) * 8;

    const int iters = K >> 6;

    float acc[2][8][4];
#pragma unroll
    for (int a = 0; a < 2; a++)
#pragma unroll
        for (int b = 0; b < 8; b++)
#pragma unroll
            for (int c = 0; c < 4; c++) acc[a][b][c] = 0.0f;

    fill_stage(shh, shh + BM * HPAD, A, Bt, bm, bn, 0, K, tid);
    CP_COMMIT();
    fill_stage(shh + STAGE_H, shh + STAGE_H + BM * HPAD, A, Bt, bm, bn, 64, K, tid);
    CP_COMMIT();

    for (int i = 0; i < iters; i++) {
        if (i + 1 < iters) { CP_WAIT(1); } else { CP_WAIT(0); }
        __syncthreads();

        if (i + 2 < iters) {
            __half* st = shh + ((i + 2) % 3) * STAGE_H;
            fill_stage(st, st + BM * HPAD, A, Bt, bm, bn, (i + 2) * 64, K, tid);
            CP_COMMIT();
        }

        const __half* As = shh + (i % 3) * STAGE_H;
        const __half* Bs = As + BM * HPAD;
#pragma unroll
        for (int ks = 0; ks < 4; ks++) {
            uint32_t af[2][4], bf[8][2];
#pragma unroll
            for (int mt = 0; mt < 2; mt++) {
                uint32_t addr = smem_u32(
                    &As[(moff + mt * 16 + a_r) * HPAD + ks * 16 + a_c]);
                ldmatrix_x4(af[mt][0], af[mt][1], af[mt][2], af[mt][3], addr);
            }
#pragma unroll
            for (int np = 0; np < 4; np++) {
                uint32_t addr = smem_u32(
                    &Bs[(noff + np * 16 + b_r) * HPAD + ks * 16 + b_c]);
                ldmatrix_x4(bf[np * 2][0], bf[np * 2][1],
                            bf[np * 2 + 1][0], bf[np * 2 + 1][1], addr);
            }
#pragma unroll
            for (int mt = 0; mt < 2; mt++)
#pragma unroll
                for (int nt = 0; nt < 8; nt++)
                    mma_f16(acc[mt][nt][0], acc[mt][nt][1], acc[mt][nt][2], acc[mt][nt][3],
                            af[mt][0], af[mt][1], af[mt][2], af[mt][3],
                            bf[nt][0], bf[nt][1]);
        }
    }

    // epilogue
#pragma unroll
    for (int nt = 0; nt < 8; nt++) {
        const int col = bn + noff + nt * 8 + 2 * t;
        const float2 bv = *(const float2*)&bias[col];
#pragma unroll
        for (int mt = 0; mt < 2; mt++) {
            const int r0 = bm + moff + mt * 16 + g;
            float c0 = acc[mt][nt][0] + bv.x;
            float c1 = acc[mt][nt][1] + bv.y;
            float c2 = acc[mt][nt][2] + bv.x;
            float c3 = acc[mt][nt][3] + bv.y;
            if (EPI == 2) {
                c0 = gelu_fn(c0); c1 = gelu_fn(c1);
                c2 = gelu_fn(c2); c3 = gelu_fn(c3);
            }
            if (EPI == 0) {
                float* C = (float*)Cout;
                *(float2*)&C[(size_t)r0 * N + col]       = make_float2(c0, c1);
                *(float2*)&C[(size_t)(r0 + 8) * N + col] = make_float2(c2, c3);
            } else {
                __half* C = (__half*)Cout;
                *(__half2*)&C[(size_t)r0 * N + col]       = __floats2half2_rn(c0, c1);
                *(__half2*)&C[(size_t)(r0 + 8) * N + col] = __floats2half2_rn(c2, c3);
            }
        }
    }
}

// ---------------------------------------------------------------------------
// Flash attention, fp16 mma. (unchanged from round 10)
// ---------------------------------------------------------------------------
#define BQ   128
#define BKV  64
#define NKB  (SEQ / BKV)
#define ATT_SMEM ((2 * BQ * HPAD + 4 * BKV * HPAD) * 2)   // 73728 B

__global__ void __launch_bounds__(256, 2) attn_mma_h_kernel(
    const __half* __restrict__ QKV, __half* __restrict__ Og)
{
    extern __shared__ __half sha[];
    __half* Qs = sha;                              // [BQ][HPAD]
    __half* Ks = sha + BQ * HPAD;                  // [2][BKV][HPAD]
    __half* Vs = sha + BQ * HPAD + 2 * BKV * HPAD; // [2][BKV][HPAD]
    __half* Ps = sha + BQ * HPAD + 4 * BKV * HPAD; // [BQ][HPAD]

    const int tid  = threadIdx.x;
    const int wid  = tid >> 5;
    const int lane = tid & 31;
    const int g    = lane >> 2;
    const int t    = lane & 3;
    const int qt   = blockIdx.x;
    const int head = blockIdx.y;
    const int b    = blockIdx.z;

    const size_t baseq = ((size_t)b * SEQ) * NQKV + (size_t)head * DK;
    const __half* Qg = QKV + baseq;
    const __half* Kg = QKV + baseq + HID;
    const __half* Vg = QKV + baseq + 2 * HID;
    const size_t baso = ((size_t)b * SEQ) * HID + (size_t)head * DK;

    const int q0   = qt * BQ;
    const int moff = wid * 16;

    const int a_r = lane & 15;
    const int a_c = (lane >> 4) * 8;
    const int b_r = (lane & 7) + ((lane >> 4) << 3);
    const int b_c = ((lane >> 3) & 1) * 8;

#pragma unroll
    for (int q = 0; q < 4; q++) {
        int idx = q * 256 + tid;
        int r = idx >> 3, c = idx & 7;
        cp_async16(smem_u32(&Qs[r * HPAD + c * 8]),
                   &Qg[(size_t)(q0 + r) * NQKV + c * 8]);
    }
#pragma unroll
    for (int q = 0; q < 2; q++) {
        int idx = q * 256 + tid;
        int r = idx >> 3, c = idx & 7;
        cp_async16(smem_u32(&Ks[r * HPAD + c * 8]),
                   &Kg[(size_t)r * NQKV + c * 8]);
        cp_async16(smem_u32(&Vs[r * HPAD + c * 8]),
                   &Vg[(size_t)r * NQKV + c * 8]);
    }
    CP_COMMIT();

    const uint32_t vlane_off = (uint32_t)((lane & 15) * HPAD + (lane >> 4) * 8);

    float oacc[8][4];
#pragma unroll
    for (int nt = 0; nt < 8; nt++)
#pragma unroll
        for (int c = 0; c < 4; c++) oacc[nt][c] = 0.0f;
    float m0 = -1e30f, m1 = -1e30f, l0 = 0.0f, l1 = 0.0f;

    for (int i = 0; i < NKB; i++) {
        if (i + 1 < NKB) {
            const int kn = (i + 1) * BKV;
            __half* Kb = Ks + ((i + 1) & 1) * BKV * HPAD;
            __half* Vb = Vs + ((i + 1) & 1) * BKV * HPAD;
#pragma unroll
            for (int q = 0; q < 2; q++) {
                int idx = q * 256 + tid;
                int r = idx >> 3, c = idx & 7;
                cp_async16(smem_u32(&Kb[r * HPAD + c * 8]),
                           &Kg[(size_t)(kn + r) * NQKV + c * 8]);
                cp_async16(smem_u32(&Vb[r * HPAD + c * 8]),
                           &Vg[(size_t)(kn + r) * NQKV + c * 8]);
            }
            CP_COMMIT();
            CP_WAIT(1);
        } else {
            CP_WAIT(0);
        }
        __syncthreads();

        const __half* Kb = Ks + (i & 1) * BKV * HPAD;
        const __half* Vb = Vs + (i & 1) * BKV * HPAD;

        float sacc[8][4];
#pragma unroll
        for (int nt = 0; nt < 8; nt++)
#pragma unroll
            for (int c = 0; c < 4; c++) sacc[nt][c] = 0.0f;

#pragma unroll
        for (int ks = 0; ks < 4; ks++) {
            uint32_t qf[4];
            {
                uint32_t addr = smem_u32(
                    &Qs[(moff + a_r) * HPAD + ks * 16 + a_c]);
                ldmatrix_x4(qf[0], qf[1], qf[2], qf[3], addr);
            }
            uint32_t bf[8][2];
#pragma unroll
            for (int np = 0; np < 4; np++) {
                uint32_t addr = smem_u32(
                    &Kb[(np * 16 + b_r) * HPAD + ks * 16 + b_c]);
                ldmatrix_x4(bf[np * 2][0], bf[np * 2][1],
                            bf[np * 2 + 1][0], bf[np * 2 + 1][1], addr);
            }
#pragma unroll
            for (int nt = 0; nt < 8; nt++)
                mma_f16(sacc[nt][0], sacc[nt][1], sacc[nt][2], sacc[nt][3],
                        qf[0], qf[1], qf[2], qf[3],
                        bf[nt][0], bf[nt][1]);
        }

        float rx0 = -1e30f, rx1 = -1e30f;
#pragma unroll
        for (int nt = 0; nt < 8; nt++) {
            sacc[nt][0] *= 0.125f; sacc[nt][1] *= 0.125f;
            sacc[nt][2] *= 0.125f; sacc[nt][3] *= 0.125f;
            rx0 = fmaxf(rx0, fmaxf(sacc[nt][0], sacc[nt][1]));
            rx1 = fmaxf(rx1, fmaxf(sacc[nt][2], sacc[nt][3]));
        }
        rx0 = fmaxf(rx0, __shfl_xor_sync(0xffffffffu, rx0, 1));
        rx0 = fmaxf(rx0, __shfl_xor_sync(0xffffffffu, rx0, 2));
        rx1 = fmaxf(rx1, __shfl_xor_sync(0xffffffffu, rx1, 1));
        rx1 = fmaxf(rx1, __shfl_xor_sync(0xffffffffu, rx1, 2));

        const float nm0 = fmaxf(m0, rx0);
        const float nm1 = fmaxf(m1, rx1);
        const float corr0 = __expf(m0 - nm0);
        const float corr1 = __expf(m1 - nm1);

        float rs0 = 0.0f, rs1 = 0.0f;
#pragma unroll
        for (int nt = 0; nt < 8; nt++) {
            sacc[nt][0] = __expf(sacc[nt][0] - nm0);
            sacc[nt][1] = __expf(sacc[nt][1] - nm0);
            sacc[nt][2] = __expf(sacc[nt][2] - nm1);
            sacc[nt][3] = __expf(sacc[nt][3] - nm1);
            rs0 += sacc[nt][0] + sacc[nt][1];
            rs1 += sacc[nt][2] + sacc[nt][3];
        }
        rs0 += __shfl_xor_sync(0xffffffffu, rs0, 1);
        rs0 += __shfl_xor_sync(0xffffffffu, rs0, 2);
        rs1 += __shfl_xor_sync(0xffffffffu, rs1, 1);
        rs1 += __shfl_xor_sync(0xffffffffu, rs1, 2);

        l0 = l0 * corr0 + rs0;  m0 = nm0;
        l1 = l1 * corr1 + rs1;  m1 = nm1;

#pragma unroll
        for (int nt = 0; nt < 8; nt++) {
            oacc[nt][0] *= corr0; oacc[nt][1] *= corr0;
            oacc[nt][2] *= corr1; oacc[nt][3] *= corr1;
        }

#pragma unroll
        for (int nt = 0; nt < 8; nt++) {
            *(__half2*)&Ps[(moff + g) * HPAD + nt * 8 + 2 * t] =
                __floats2half2_rn(sacc[nt][0], sacc[nt][1]);
            *(__half2*)&Ps[(moff + 8 + g) * HPAD + nt * 8 + 2 * t] =
                __floats2half2_rn(sacc[nt][2], sacc[nt][3]);
        }
        __syncwarp();

        const uint32_t vbase = smem_u32(Vb) + vlane_off * 2;
#pragma unroll
        for (int ks = 0; ks < 4; ks++) {
            const int kc = ks * 16 + 2 * t;
            const uint32_t a0 = *(const uint32_t*)&Ps[(moff + g) * HPAD + kc];
            const uint32_t a1 = *(const uint32_t*)&Ps[(moff + 8 + g) * HPAD + kc];
            const uint32_t a2 = *(const uint32_t*)&Ps[(moff + g) * HPAD + kc + 8];
            const uint32_t a3 = *(const uint32_t*)&Ps[(moff + 8 + g) * HPAD + kc + 8];
            const uint32_t vrow = vbase + (uint32_t)(ks * 16 * HPAD * 2);
#pragma unroll
            for (int n16 = 0; n16 < 4; n16++) {
                uint32_t r0, r1, r2, r3;
                ldmatrix_x4_trans(r0, r1, r2, r3, vrow + (uint32_t)(n16 * 32));
                mma_f16(oacc[n16 * 2][0], oacc[n16 * 2][1], oacc[n16 * 2][2], oacc[n16 * 2][3],
                        a0, a1, a2, a3, r0, r1);
                mma_f16(oacc[n16 * 2 + 1][0], oacc[n16 * 2 + 1][1],
                        oacc[n16 * 2 + 1][2], oacc[n16 * 2 + 1][3],
                        a0, a1, a2, a3, r2, r3);
            }
        }
        __syncthreads();
    }

    const float inv0 = 1.0f / l0;
    const float inv1 = 1.0f / l1;
    const int r0 = q0 + moff + g;
    const int r1 = r0 + 8;
#pragma unroll
    for (int nt = 0; nt < 8; nt++) {
        const int col = nt * 8 + 2 * t;
        *(__half2*)&Og[baso + (size_t)r0 * HID + col] =
            __floats2half2_rn(oacc[nt][0] * inv0, oacc[nt][1] * inv0);
        *(__half2*)&Og[baso + (size_t)r1 * HID + col] =
            __floats2half2_rn(oacc[nt][2] * inv1, oacc[nt][3] * inv1);
    }
}

// ---------------------------------------------------------------------------
// Residual add + LayerNorm (optionally also emits a half copy)
// ---------------------------------------------------------------------------
template<int HALF_OUT>
__global__ void __launch_bounds__(256) add_ln_kernel(
    const float* __restrict__ X, const float* __restrict__ Y,
    const float* __restrict__ g, const float* __restrict__ be,
    float* __restrict__ out, __half* __restrict__ outh)
{
    const int row = blockIdx.x;
    const int tid = threadIdx.x;
    const size_t base = (size_t)row * HID;

    float v[4];
    float s = 0.0f, s2 = 0.0f;
#pragma unroll
    for (int k = 0; k < 4; k++) {
        int c = tid + k * 256;
        float tt = X[base + c] + Y[base + c];
        v[k] = tt;
        s += tt;
        s2 += tt * tt;
    }
#pragma unroll
    for (int off = 16; off > 0; off >>= 1) {
        s  += __shfl_xor_sync(0xffffffffu, s,  off);
        s2 += __shfl_xor_sync(0xffffffffu, s2, off);
    }
    __shared__ float red[16];
    const int warp = tid >> 5, lane = tid & 31;
    if (lane == 0) { red[warp] = s; red[warp + 8] = s2; }
    __syncthreads();
    if (tid < 32) {
        float a = (lane < 8) ? red[lane]     : 0.0f;
        float c2 = (lane < 8) ? red[lane + 8] : 0.0f;
#pragma unroll
        for (int off = 4; off > 0; off >>= 1) {
            a  += __shfl_xor_sync(0xffffffffu, a,  off);
            c2 += __shfl_xor_sync(0xffffffffu, c2, off);
        }
        if (lane == 0) { red[0] = a; red[1] = c2; }
    }
    __syncthreads();
    const float mu  = red[0] * (1.0f / HID);
    const float var = red[1] * (1.0f / HID) - mu * mu;
    const float inv = rsqrtf(var + 1e-5f);
#pragma unroll
    for (int k = 0; k < 4; k++) {
        int c = tid + k * 256;
        float r = (v[k] - mu) * inv * g[c] + be[c];
        out[base + c] = r;
        if (HALF_OUT) outh[base + c] = __float2half_rn(r);
    }
}

// ---------------------------------------------------------------------------
// kernel_launch
// ---------------------------------------------------------------------------
extern "C" void kernel_launch(void* const* d_in, const int* in_sizes, int n_in,
                              void* d_out, int out_size)
{
    const float* x  = (const float*)d_in[0];
    const float* Wq = (const float*)d_in[1];
    const float* bq = (const float*)d_in[2];
    const float* Wk = (const float*)d_in[3];
    const float* bk = (const float*)d_in[4];
    const float* Wv = (const float*)d_in[5];
    const float* bv = (const float*)d_in[6];
    const float* Wo = (const float*)d_in[7];
    const float* bo = (const float*)d_in[8];
    const float* W1 = (const float*)d_in[9];
    const float* b1 = (const float*)d_in[10];
    const float* W2 = (const float*)d_in[11];
    const float* b2 = (const float*)d_in[12];
    const float* g1 = (const float*)d_in[13];
    const float* be1= (const float*)d_in[14];
    const float* g2 = (const float*)d_in[15];
    const float* be2= (const float*)d_in[16];
    float* out = (float*)d_out;

    __half *xh, *qkvh, *ctxh, *x1h, *hh;
    float *ao, *x1, *ff, *bqkv;
    __half *wqkvt, *wot, *w1t, *w2t;
    cudaGetSymbolAddress((void**)&xh,    g_xh);
    cudaGetSymbolAddress((void**)&qkvh,  g_qkvh);
    cudaGetSymbolAddress((void**)&ctxh,  g_ctxh);
    cudaGetSymbolAddress((void**)&ao,    g_ao);
    cudaGetSymbolAddress((void**)&x1,    g_x1);
    cudaGetSymbolAddress((void**)&x1h,   g_x1h);
    cudaGetSymbolAddress((void**)&hh,    g_hh);
    cudaGetSymbolAddress((void**)&ff,    g_ff);
    cudaGetSymbolAddress((void**)&wqkvt, g_wqkvt);
    cudaGetSymbolAddress((void**)&wot,   g_wot);
    cudaGetSymbolAddress((void**)&w1t,   g_w1t);
    cudaGetSymbolAddress((void**)&w2t,   g_w2t);
    cudaGetSymbolAddress((void**)&bqkv,  g_bqkv);

    cudaFuncSetAttribute(attn_mma_h_kernel,
                         cudaFuncAttributeMaxDynamicSharedMemorySize, ATT_SMEM);
    cudaFuncSetAttribute(mma_gemm_h<0>,
                         cudaFuncAttributeMaxDynamicSharedMemorySize, GEMM_SMEM);
    cudaFuncSetAttribute(mma_gemm_h<1>,
                         cudaFuncAttributeMaxDynamicSharedMemorySize, GEMM_SMEM);
    cudaFuncSetAttribute(mma_gemm_h<2>,
                         cudaFuncAttributeMaxDynamicSharedMemorySize, GEMM_SMEM);

    const dim3 blk256(256);
    const dim3 blk512(NTHR);

    // single fused prep launch
    prep_kernel<<<16396, blk256>>>(Wq, Wk, Wv, Wo, W1, W2, x, bq, bk, bv);

    // fused QKV GEMM  (8192 x 3072 x 1024)
    mma_gemm_h<1><<<dim3(NQKV / BN, MTOT / BM), blk512, GEMM_SMEM>>>(
        xh, wqkvt, bqkv, qkvh, MTOT, NQKV, HID);

    // attention
    attn_mma_h_kernel<<<dim3(SEQ / BQ, NHEAD, BATCH), blk256, ATT_SMEM>>>(qkvh, ctxh);

    const dim3 gProj(HID / BN, MTOT / BM);   // (4, 64)
    const dim3 gFF1 (DFF / BN, MTOT / BM);   // (16, 64)

    // Output projection (fp32 out) + residual/LN1 (emit half copy for FF1)
    mma_gemm_h<0><<<gProj, blk512, GEMM_SMEM>>>(ctxh, wot, bo, ao, MTOT, HID, HID);
    add_ln_kernel<1><<<MTOT, blk256>>>(x, ao, g1, be1, x1, x1h);

    // FFN
    mma_gemm_h<2><<<gFF1, blk512, GEMM_SMEM>>>(x1h, w1t, b1, hh, MTOT, DFF, HID);
    mma_gemm_h<0><<<gProj, blk512, GEMM_SMEM>>>(hh, w2t, b2, ff, MTOT, HID, DFF);

    // Residual/LN2 -> output
    add_ln_kernel<0><<<MTOT, blk256>>>(x1, ff, g2, be2, out, nullptr);
}